// round 16
// baseline (speedup 1.0000x reference)
#include <cuda_runtime.h>
#include <cuda_bf16.h>
#include <cstdint>

// Segment-sum of weighted RGB over sorted ray indices.
// Persistent kernel with 4-stage cp.async.bulk (TMA/UBLKCP) pipeline:
// the TMA engine's outstanding capacity replaces the per-SM LDG queue
// (~60 reqs) that has capped every LDG-based variant at ~4.4 TB/s.

#define BLOCK 512
#define IPT 4
#define TILE (BLOCK * IPT)                  // 2048 samples
#define STAGES 4
#define RGB_BYTES (TILE * 12)               // 24576
#define W_BYTES   (TILE * 4)                // 8192
#define IDX_BYTES (TILE * 4)                // 8192
#define STAGE_BYTES (RGB_BYTES + W_BYTES + IDX_BYTES)   // 40960
#define SMEM_BYTES (STAGES * STAGE_BYTES)               // 163840
#define GRID 148

__global__ void zero_out_kernel4(float4* __restrict__ out, int n4) {
    int i = blockIdx.x * blockDim.x + threadIdx.x;
    if (i < n4) out[i] = make_float4(0.f, 0.f, 0.f, 0.f);
}
__global__ void zero_out_tail(float* __restrict__ out, int start, int n) {
    int i = start + blockIdx.x * blockDim.x + threadIdx.x;
    if (i < n) out[i] = 0.0f;
}

__device__ __forceinline__ uint32_t smem_u32(const void* p) {
    return (uint32_t)__cvta_generic_to_shared(p);
}
__device__ __forceinline__ void mbar_init(uint32_t mbar, uint32_t count) {
    asm volatile("mbarrier.init.shared.b64 [%0], %1;" :: "r"(mbar), "r"(count) : "memory");
}
__device__ __forceinline__ void mbar_expect_tx(uint32_t mbar, uint32_t bytes) {
    asm volatile("mbarrier.arrive.expect_tx.shared.b64 _, [%0], %1;"
                 :: "r"(mbar), "r"(bytes) : "memory");
}
__device__ __forceinline__ void mbar_wait(uint32_t mbar, uint32_t parity) {
    uint32_t done;
    asm volatile(
        "{\n\t.reg .pred p;\n\t"
        "mbarrier.try_wait.parity.acquire.cta.shared::cta.b64 p, [%1], %2;\n\t"
        "selp.b32 %0, 1, 0, p;\n\t}"
        : "=r"(done) : "r"(mbar), "r"(parity) : "memory");
    if (!done) {
        asm volatile(
            "{\n\t.reg .pred P1;\n\t"
            "WAIT_LOOP_%=:\n\t"
            "mbarrier.try_wait.parity.acquire.cta.shared::cta.b64 P1, [%0], %1, 0x989680;\n\t"
            "@P1 bra.uni WAIT_DONE_%=;\n\t"
            "bra.uni WAIT_LOOP_%=;\n\t"
            "WAIT_DONE_%=:\n\t}"
            :: "r"(mbar), "r"(parity) : "memory");
    }
}
__device__ __forceinline__ void bulk_cp(uint32_t sdst, const void* gsrc,
                                        uint32_t bytes, uint32_t mbar) {
    asm volatile(
        "cp.async.bulk.shared::cta.global.mbarrier::complete_tx::bytes "
        "[%0], [%1], %2, [%3];"
        :: "r"(sdst), "l"(gsrc), "r"(bytes), "r"(mbar) : "memory");
}

__global__ __launch_bounds__(BLOCK, 1) void integrate_kernel(
    const float* __restrict__ rgbf,   // [N*3]
    const float* __restrict__ wf,     // [N]
    const int*   __restrict__ idxf,   // [N]
    float* __restrict__ out,
    int n_samples)
{
    extern __shared__ __align__(128) unsigned char smem[];
    __shared__ __align__(8) unsigned long long fullbar[STAGES];

    const int tid = threadIdx.x;
    const int n_tiles = n_samples / TILE;

    if (tid == 0) {
#pragma unroll
        for (int s = 0; s < STAGES; s++)
            mbar_init(smem_u32(&fullbar[s]), 1);
    }
    __syncthreads();

    // tiles owned by this block: blockIdx.x, +GRID, ...
    int my_n = 0;
    for (int t = blockIdx.x; t < n_tiles; t += GRID) my_n++;

    auto issue = [&](int j, int s) {   // fetch my j-th tile into stage s
        long tile = (long)blockIdx.x + (long)j * GRID;
        uint32_t sb = smem_u32(smem) + s * STAGE_BYTES;
        uint32_t mb = smem_u32(&fullbar[s]);
        mbar_expect_tx(mb, STAGE_BYTES);
        bulk_cp(sb,                       rgbf + tile * (TILE * 3), RGB_BYTES, mb);
        bulk_cp(sb + RGB_BYTES,           wf   + tile * TILE,       W_BYTES,   mb);
        bulk_cp(sb + RGB_BYTES + W_BYTES, idxf + tile * TILE,       IDX_BYTES, mb);
    };

    if (tid == 0) {
        int pre = my_n < STAGES ? my_n : STAGES;
        for (int j = 0; j < pre; j++) issue(j, j);
    }
    __syncthreads();

    for (int j = 0; j < my_n; j++) {
        const int s = j & (STAGES - 1);
        const uint32_t parity = (uint32_t)(j >> 2) & 1u;
        mbar_wait(smem_u32(&fullbar[s]), parity);

        const unsigned char* st = smem + s * STAGE_BYTES;
        const float4* rgb4 = (const float4*)st;
        const float4* w4   = (const float4*)(st + RGB_BYTES);
        const int4*   i4   = (const int4*)(st + RGB_BYTES + W_BYTES);

        float4 r0 = rgb4[3 * tid + 0];
        float4 r1 = rgb4[3 * tid + 1];
        float4 r2 = rgb4[3 * tid + 2];
        float4 wv = w4[tid];
        int4   iv = i4[tid];

        float rf[12] = {r0.x, r0.y, r0.z, r0.w,
                        r1.x, r1.y, r1.z, r1.w,
                        r2.x, r2.y, r2.z, r2.w};
        float w[IPT]  = {wv.x, wv.y, wv.z, wv.w};
        int  idx[IPT] = {iv.x, iv.y, iv.z, iv.w};

        int cur = idx[0];
        float a0 = 0.f, a1 = 0.f, a2 = 0.f;
#pragma unroll
        for (int k = 0; k < IPT; k++) {
            int ik = idx[k];
            if (ik != cur) {
                atomicAdd(&out[3 * cur + 0], a0);
                atomicAdd(&out[3 * cur + 1], a1);
                atomicAdd(&out[3 * cur + 2], a2);
                cur = ik;
                a0 = a1 = a2 = 0.f;
            }
            a0 = fmaf(w[k], rf[3 * k + 0], a0);
            a1 = fmaf(w[k], rf[3 * k + 1], a1);
            a2 = fmaf(w[k], rf[3 * k + 2], a2);
        }
        atomicAdd(&out[3 * cur + 0], a0);
        atomicAdd(&out[3 * cur + 1], a1);
        atomicAdd(&out[3 * cur + 2], a2);

        __syncthreads();                       // stage fully consumed
        if (tid == 0 && j + STAGES < my_n)     // refill this stage slot
            issue(j + STAGES, s);
    }

    // tail samples beyond full tiles
    long tail = (long)n_tiles * TILE;
    for (long i = tail + (long)blockIdx.x * BLOCK + tid; i < n_samples;
         i += (long)GRID * BLOCK) {
        int r = idxf[i];
        float ws = wf[i];
        atomicAdd(&out[3 * r + 0], ws * rgbf[3 * i + 0]);
        atomicAdd(&out[3 * r + 1], ws * rgbf[3 * i + 1]);
        atomicAdd(&out[3 * r + 2], ws * rgbf[3 * i + 2]);
    }
}

extern "C" void kernel_launch(void* const* d_in, const int* in_sizes, int n_in,
                              void* d_out, int out_size) {
    const float* rgb = (const float*)d_in[0];
    const float* wts = (const float*)d_in[1];
    const int*   idx = (const int*)d_in[2];
    float* out = (float*)d_out;

    int n_samples = in_sizes[2];

    // zero-init output (poisoned by harness; empty rays must be 0)
    {
        int n4 = out_size / 4;
        int threads = 256;
        int blocks = (n4 + threads - 1) / threads;
        if (blocks > 0)
            zero_out_kernel4<<<blocks, threads>>>((float4*)out, n4);
        if (out_size - n4 * 4 > 0)
            zero_out_tail<<<1, 32>>>(out, n4 * 4, out_size);
    }

    cudaFuncSetAttribute(integrate_kernel,
                         cudaFuncAttributeMaxDynamicSharedMemorySize,
                         SMEM_BYTES);
    integrate_kernel<<<GRID, BLOCK, SMEM_BYTES>>>(rgb, wts, idx, out, n_samples);
}